// round 7
// baseline (speedup 1.0000x reference)
#include <cuda_runtime.h>
#include <math.h>

#define BN 4
#define HH 96
#define WW 96
#define NN (HH*WW)        // 9216
#define EH (HH*(WW-1))    // 9120
#define EV ((HH-1)*WW)    // 9120
#define EE (EH+EV)        // 18240  (< 2^15)
#define NCH 21
#define CLOW 3
#define CHIGH 512
#define NGROUP 11         // DP channel groups: 10 groups of 2 real + 1 group of 1
#define DP_T 256
#define CBCAP 2560
#define DP_SMEM (3*NN*4 + NN*4 + NN*8 + CBCAP*4)   // A + wv + recs + cboff = 231424 B
#define CH_SMEM (3*NN*4)                            // tp + chq + np = 110592 B
#define BFS_SMEM (NN + 3*NN*4)                      // flags + ord + par + topo = 119808 B
#define SMEM_BORUVKA (NN*16)                        // bw(8) + cp(4) + lk(4) = 147456 B

// ---------------- device scratch ----------------
__device__ float  g_prob[BN*NCH*NN];
__device__ float  g_AS2 [BN*NCH*NN];
__device__ float  g_hft [(size_t)BN*NN*CHIGH];      // high feats transposed [b][n][c]
__device__ unsigned long long g_wkey[2][BN*EE];     // fused (weight_bits & ~0x7FFF) | edge
__device__ int    g_mst [2][BN*EE];
__device__ int    g_ord [2][BN*NN];       // BFS position -> node
__device__ int    g_par [2][BN*NN];       // node -> parent node (-1 root)
__device__ unsigned g_topo[2][BN*NN];     // BFS pos -> pp | cs<<14 | cn<<28
// chain structures (chain-pos indexed)
__device__ int    g_ordC[2][BN*NN];       // chain pos -> node
__device__ uint2  g_crec[2][BN*NN];       // chain records
__device__ int    g_cboff[2][BN*(NN+2)];  // bucket offsets over rec indices
__device__ int    g_ncb [2][BN];          // #buckets
__device__ int    g_nrec[2][BN];          // #chains
__device__ float  g_wposC[2][BN*NN];      // chain pos -> parent-edge weight (root 0)
__device__ int    g_posNC1[BN*NN];        // tree1: node -> chain pos
__device__ int    g_perm01[BN*NN];        // tree0 chain pos -> tree1 chain pos
__device__ float  g_f0[BN*NCH*NN];        // stage0 features [b][c][cpos0]
__device__ float  g_f1[BN*NCH*NN];        // stage1 features [b][c][cpos1]
__device__ double g_acc[2];

__device__ __forceinline__ void edge_ep(int e, int& a, int& b) {
    if (e < EH) { int r = e / (WW-1), c = e % (WW-1); a = r*WW + c; b = a + 1; }
    else        { int j = e - EH;                      a = j;        b = j + WW; }
}
__device__ __forceinline__ void twosum(float& s, float& comp, float p) {
    float t = s + p;
    float z = t - s;
    float e = (s - (t - z)) + (p - z);
    s = t; comp += e;
}
__device__ __forceinline__ unsigned long long fuse_key(double w, int e) {
    return ((unsigned long long)__double_as_longlong(w) & 0xFFFFFFFFFFFF8000ull)
           | (unsigned long long)e;
}

// ---------------- kernels ----------------

__global__ void k_sigmoid(const float* __restrict__ preds) {
    int i = blockIdx.x*blockDim.x + threadIdx.x;
    if (i < BN*NCH*NN) g_prob[i] = 1.0f / (1.0f + expf(-preds[i]));
}

__global__ void k_transpose(const float* __restrict__ hf) {
    __shared__ float tile[32][33];
    int b = blockIdx.z;
    int n0 = blockIdx.x*32, c0 = blockIdx.y*32;
    const float* src = hf + (size_t)b*CHIGH*NN;
    tile[threadIdx.y][threadIdx.x] = src[(size_t)(c0+threadIdx.y)*NN + n0+threadIdx.x];
    __syncthreads();
    g_hft[((size_t)b*NN + n0+threadIdx.y)*CHIGH + c0+threadIdx.x] = tile[threadIdx.x][threadIdx.y];
}

__global__ void k_edgew_low(const float* __restrict__ feat) {
    int i = blockIdx.x*blockDim.x + threadIdx.x;
    if (i >= BN*EE) return;
    int b = i / EE, e = i % EE;
    int a, bb; edge_ep(e, a, bb);
    const float* f = feat + (size_t)b * CLOW * NN;
    double s = 0.0;
    #pragma unroll
    for (int c = 0; c < CLOW; c++) {
        double d = (double)f[c*NN + a] - (double)f[c*NN + bb];
        s += d * d;
    }
    g_wkey[0][i] = fuse_key(s, e);
}

__global__ __launch_bounds__(256) void k_edgew_high() {
    int w = (blockIdx.x*blockDim.x + threadIdx.x) >> 5;
    int lane = threadIdx.x & 31;
    if (w >= BN*EE) return;
    int b = w / EE, e = w % EE;
    int a, bb; edge_ep(e, a, bb);
    const float4* fa = (const float4*)(g_hft + ((size_t)b*NN + a)*CHIGH);
    const float4* fb = (const float4*)(g_hft + ((size_t)b*NN + bb)*CHIGH);
    float s = 0.f, comp = 0.f;
    #pragma unroll
    for (int k = 0; k < 4; k++) {
        float4 x = fa[lane + 32*k];
        float4 y = fb[lane + 32*k];
        float d0 = x.x - y.x, d1 = x.y - y.y, d2 = x.z - y.z, d3 = x.w - y.w;
        twosum(s, comp, d0*d0);
        twosum(s, comp, d1*d1);
        twosum(s, comp, d2*d2);
        twosum(s, comp, d3*d3);
    }
    double v = (double)s + (double)comp;
    #pragma unroll
    for (int off = 16; off; off >>= 1) v += __shfl_down_sync(0xffffffffu, v, off);
    if (lane == 0) g_wkey[1][w] = fuse_key(v, e);
}

// Boruvka MST, single-phase fused keys, smem scratch.
__global__ __launch_bounds__(1024) void k_boruvka_both() {
    int b = blockIdx.x & 3, tree = blockIdx.x >> 2;
    int tid = threadIdx.x, T = blockDim.x;
    const unsigned long long* wk = g_wkey[tree] + b*EE;
    int* mf = g_mst[tree] + b*EE;

    extern __shared__ char smraw[];
    unsigned long long* bw = (unsigned long long*)smraw;
    int* cp = (int*)(smraw + NN*8);
    int* lk = cp + NN;

    for (int v = tid; v < NN; v += T) cp[v] = v;
    for (int e = tid; e < EE; e += T) mf[e] = 0;
    __syncthreads();

    __shared__ int s_any, s_chg;
    for (int round = 0; round < 14; round++) {
        for (int v = tid; v < NN; v += T) {
            bw[v] = 0xFFFFFFFFFFFFFFFFull;
            lk[v] = v;
        }
        if (tid == 0) s_any = 0;
        __syncthreads();

        for (int e = tid; e < EE; e += T) {
            int a, bb; edge_ep(e, a, bb);
            int ca = cp[a], cb = cp[bb];
            if (ca != cb) {
                unsigned long long k = wk[e];
                atomicMin(&bw[ca], k);
                atomicMin(&bw[cb], k);
                s_any = 1;
            }
        }
        __syncthreads();
        if (!s_any) break;

        for (int v = tid; v < NN; v += T) {
            if (cp[v] == v && bw[v] != 0xFFFFFFFFFFFFFFFFull) {
                int e = (int)(bw[v] & 0x7FFFull);
                int a, bb; edge_ep(e, a, bb);
                int ca = cp[a], cb = cp[bb];
                lk[v] = (ca == v) ? cb : ca;
                mf[e] = 1;
            }
        }
        __syncthreads();

        for (int v = tid; v < NN; v += T) {
            int o = lk[v];
            if (o != v && lk[o] == v && v < o) lk[v] = v;
        }
        __syncthreads();

        for (int it = 0; it < 20; it++) {
            if (tid == 0) s_chg = 0;
            __syncthreads();
            for (int v = tid; v < NN; v += T) {
                int l = lk[v]; int ll = lk[l];
                if (l != ll) { lk[v] = ll; s_chg = 1; }
            }
            __syncthreads();
            if (!s_chg) break;
        }
        for (int v = tid; v < NN; v += T) cp[v] = lk[cp[v]];
        __syncthreads();
    }
}

// BFS rooting with contiguous child ranges + packed topology, smem state.
__global__ __launch_bounds__(256) void k_bfs_both() {
    int b = blockIdx.x & 3, tr = blockIdx.x >> 2;
    int tid = threadIdx.x, T = blockDim.x;
    extern __shared__ char sm[];
    unsigned char* flg = (unsigned char*)sm;        // NN
    int* ord = (int*)(sm + NN);                     // NN
    int* par = ord + NN;                            // NN
    unsigned* topo = (unsigned*)(par + NN);         // NN
    const int* mf = g_mst[tr] + b*EE;

    for (int v = tid; v < NN; v += T) {
        int r = v / WW, c = v % WW;
        unsigned f = 0;
        if (c > 0      && mf[r*(WW-1) + c - 1])  f |= 1u;
        if (c < WW-1   && mf[r*(WW-1) + c])      f |= 2u;
        if (r > 0      && mf[EH + (r-1)*WW + c]) f |= 4u;
        if (r < HH-1   && mf[EH + r*WW + c])     f |= 8u;
        flg[v] = (unsigned char)f;
        topo[v] = 0u;
    }
    __shared__ int s_cnt;
    if (tid == 0) { ord[0] = 0; par[0] = -1; }
    __syncthreads();

    int cur = 0, end = 1;
    while (true) {
        if (tid == 0) s_cnt = 0;
        __syncthreads();
        for (int i = cur + tid; i < end; i += T) {
            int u = ord[i]; int pu = par[u];
            unsigned f = flg[u];
            int tmp[4]; int m = 0;
            if (f & 1u)  { int nb = u - 1;  if (nb != pu) tmp[m++] = nb; }
            if (f & 2u)  { int nb = u + 1;  if (nb != pu) tmp[m++] = nb; }
            if (f & 4u)  { int nb = u - WW; if (nb != pu) tmp[m++] = nb; }
            if (f & 8u)  { int nb = u + WW; if (nb != pu) tmp[m++] = nb; }
            int base = end + atomicAdd(&s_cnt, m);
            topo[i] |= ((unsigned)base << 14) | ((unsigned)m << 28);
            for (int j = 0; j < m; j++) {
                ord[base + j] = tmp[j];
                par[tmp[j]] = u;
                topo[base + j] = (unsigned)i;   // pp field
            }
        }
        __syncthreads();
        int cnt = s_cnt;
        if (cnt == 0) break;
        cur = end; end += cnt;
        __syncthreads();
    }
    __syncthreads();
    for (int v = tid; v < NN; v += T) {
        g_ord[tr][b*NN + v] = ord[v];
        g_par[tr][b*NN + v] = par[v];
        g_topo[tr][b*NN + v] = topo[v];
    }
}

// Chain decomposition: BFS over chains of the rooted tree.
// Chain = maximal single-child path. Chain positions are consecutive
// top-to-bottom. Records: x = top | len<<14 | ccnt<<28 ; y = parent | fc<<14.
__global__ __launch_bounds__(256) void k_chains() {
    int b = blockIdx.x & 3, tr = blockIdx.x >> 2;
    int tid = threadIdx.x, T = blockDim.x;
    extern __shared__ char smc[];
    unsigned* tp = (unsigned*)smc;           // NN  (BFS-pos topo)
    int* chq     = (int*)(smc + NN*4);       // NN  (chain top BFS positions)
    int* np      = (int*)(smc + 2*NN*4);     // NN  (BFS pos -> chain pos)

    for (int i = tid; i < NN; i += T) tp[i] = g_topo[tr][b*NN + i];
    __shared__ int s_rec, s_pos;
    if (tid == 0) { chq[0] = 0; s_rec = 1; s_pos = 0; g_cboff[tr][b*(NN+2)] = 0; }
    __syncthreads();

    int head = 0, tail = 1, d = 0;
    while (head < tail) {
        for (int idx = head + tid; idx < tail; idx += T) {
            int top = chq[idx];
            // find chain length + bottom
            int len = 1, j = top;
            unsigned t = tp[j];
            while (((t >> 28) & 0xFu) == 1u) {
                j = (t >> 14) & 0x3FFF;
                t = tp[j];
                len++;
            }
            int ccnt = (int)(t >> 28);
            int base = atomicAdd(&s_pos, len);
            // label nodes with consecutive chain positions
            int jj = top;
            for (int k = 0; k < len; k++) {
                np[jj] = base + k;
                int node = g_ord[tr][b*NN + jj];
                g_ordC[tr][b*NN + base + k] = node;
                if (tr == 1) g_posNC1[b*NN + node] = base + k;
                jj = (tp[jj] >> 14) & 0x3FFF;
            }
            // enqueue child chains (tops = contiguous BFS child range of bottom)
            int fc = 0;
            if (ccnt > 0) {
                fc = atomicAdd(&s_rec, ccnt);
                int cs = (t >> 14) & 0x3FFF;
                for (int k = 0; k < ccnt; k++) chq[fc + k] = cs + k;
            }
            int parentNew = (top == 0) ? 0x3FFF : np[tp[top] & 0x3FFF];
            g_crec[tr][b*NN + idx] = make_uint2(
                (unsigned)base | ((unsigned)len << 14) | ((unsigned)ccnt << 28),
                (unsigned)parentNew | ((unsigned)fc << 14));
        }
        __syncthreads();
        head = tail;
        tail = s_rec;
        d++;
        if (tid == 0) g_cboff[tr][b*(NN+2) + d] = tail;
        __syncthreads();
    }
    if (tid == 0) { g_ncb[tr][b] = d; g_nrec[tr][b] = tail; }
}

// node weights at chain positions. low: thread per position.
__global__ void k_nodew_low(const float* __restrict__ feat) {
    int i = blockIdx.x*blockDim.x + threadIdx.x;
    if (i >= BN*NN) return;
    int b = i / NN;
    int v = g_ordC[0][i];
    int pu = g_par[0][b*NN + v];
    float wv = 0.0f;
    if (pu >= 0) {
        const float* f = feat + (size_t)b * CLOW * NN;
        float ss = 0.0f;
        #pragma unroll
        for (int c = 0; c < CLOW; c++) {
            float d = f[c*NN + v] - f[c*NN + pu];
            ss += d * d;
        }
        wv = expf(-ss / 0.02f);
    }
    g_wposC[0][i] = wv;
}

__global__ __launch_bounds__(256) void k_nodew_high() {
    int w = (blockIdx.x*blockDim.x + threadIdx.x) >> 5;
    int lane = threadIdx.x & 31;
    if (w >= BN*NN) return;
    int b = w / NN;
    int v = g_ordC[1][w];
    int pu = g_par[1][b*NN + v];
    float wv = 0.0f;
    if (pu >= 0) {
        const float4* fa = (const float4*)(g_hft + ((size_t)b*NN + v)*CHIGH);
        const float4* fb = (const float4*)(g_hft + ((size_t)b*NN + pu)*CHIGH);
        float ss = 0.0f;
        #pragma unroll
        for (int k = 0; k < 4; k++) {
            float4 x = fa[lane + 32*k];
            float4 y = fb[lane + 32*k];
            float d0 = x.x - y.x, d1 = x.y - y.y, d2 = x.z - y.z, d3 = x.w - y.w;
            ss += d0*d0 + d1*d1 + d2*d2 + d3*d3;
        }
        #pragma unroll
        for (int off = 16; off; off >>= 1) ss += __shfl_down_sync(0xffffffffu, ss, off);
        wv = expf(-ss);
    }
    if (lane == 0) g_wposC[1][w] = wv;
}

__global__ void k_perm01() {
    int i = blockIdx.x*blockDim.x + threadIdx.x;
    if (i < BN*NN) g_perm01[i] = g_posNC1[(i/NN)*NN + g_ordC[0][i]];
}
__global__ void k_permute0() {
    int i = blockIdx.x*blockDim.x + threadIdx.x;
    if (i >= BN*NN) return;
    int b = i / NN;
    int u = g_ordC[0][i];
    #pragma unroll
    for (int c = 0; c < NCH; c++)
        g_f0[((size_t)b*NCH + c)*NN + (i % NN)] = g_prob[((size_t)b*NCH + c)*NN + u];
}

// Chain-based two-stage tree DP: thread walks a chain with register carry.
__global__ __launch_bounds__(DP_T) void k_treedp() {
    int b = blockIdx.x / NGROUP, g = blockIdx.x % NGROUP;
    int tid = threadIdx.x;
    int nreal = (g == NGROUP-1) ? 1 : 2;
    int cbase = g*2;
    int CHp = nreal + 1;   // planes incl. norm (norm at plane nreal)

    extern __shared__ char smraw2[];
    float* A    = (float*)smraw2;                    // 3*NN
    float* wv   = (float*)(smraw2 + 3*NN*4);         // NN
    uint2* rec  = (uint2*)(smraw2 + 4*NN*4);         // NN
    int*   cb   = (int*)(smraw2 + 4*NN*4 + NN*8);    // CBCAP

    for (int st = 0; st < 2; st++) {
        const int tr = st;
        const float* FP = (st == 0 ? g_f0 : g_f1) + (size_t)b*NCH*NN;
        int nb = g_ncb[tr][b];
        int ncr = g_nrec[tr][b];

        for (int i = tid; i < NN; i += DP_T) wv[i] = g_wposC[tr][b*NN + i];
        for (int i = tid; i < ncr; i += DP_T) rec[i] = g_crec[tr][b*NN + i];
        int cbe = nb + 1; if (cbe > CBCAP) cbe = CBCAP;
        for (int i = tid; i < cbe; i += DP_T) cb[i] = g_cboff[tr][b*(NN+2) + i];
        for (int c = 0; c < nreal; c++)
            for (int i = tid; i < NN; i += DP_T) A[c*NN + i] = FP[(size_t)(cbase + c)*NN + i];
        for (int i = tid; i < NN; i += DP_T) A[nreal*NN + i] = 1.0f;
        __syncthreads();

        #define CBGET(dd) ((dd) < CBCAP ? cb[dd] : g_cboff[tr][b*(NN+2) + (dd)])
        // up pass: deepest buckets first
        for (int db = nb - 1; db >= 0; db--) {
            int lo = CBGET(db), hi = CBGET(db+1);
            for (int r = lo + tid; r < hi; r += DP_T) {
                uint2 rc = rec[r];
                int top = rc.x & 0x3FFF, len = (rc.x >> 14) & 0x3FFF;
                int ccnt = (int)(rc.x >> 28);
                int fc = (rc.y >> 14) & 0x3FFF;
                int bottom = top + len - 1;
                float a0, a1, a2;
                a0 = A[bottom];
                a1 = A[NN + bottom];
                a2 = (CHp > 2) ? A[2*NN + bottom] : 0.f;
                for (int k = 0; k < ccnt; k++) {
                    int q = rec[fc + k].x & 0x3FFF;
                    float wq = wv[q];
                    a0 += wq * A[q];
                    a1 += wq * A[NN + q];
                    if (CHp > 2) a2 += wq * A[2*NN + q];
                }
                A[bottom] = a0;
                A[NN + bottom] = a1;
                if (CHp > 2) A[2*NN + bottom] = a2;
                for (int j = bottom - 1; j >= top; j--) {
                    float wj = wv[j + 1];
                    a0 = A[j] + wj * a0;           A[j] = a0;
                    a1 = A[NN + j] + wj * a1;      A[NN + j] = a1;
                    if (CHp > 2) { a2 = A[2*NN + j] + wj * a2; A[2*NN + j] = a2; }
                }
            }
            __syncthreads();
        }
        // down pass: root bucket first (in place)
        for (int db = 0; db < nb; db++) {
            int lo = CBGET(db), hi = CBGET(db+1);
            for (int r = lo + tid; r < hi; r += DP_T) {
                uint2 rc = rec[r];
                int top = rc.x & 0x3FFF, len = (rc.x >> 14) & 0x3FFF;
                int pn = rc.y & 0x3FFF;
                float s0, s1, s2 = 0.f;
                if (pn == 0x3FFF) {
                    s0 = A[top]; s1 = A[NN + top];
                    if (CHp > 2) s2 = A[2*NN + top];
                } else {
                    float w = wv[top];
                    float a = A[top];          s0 = a + w * (A[pn] - w * a);          A[top] = s0;
                    a = A[NN + top];           s1 = a + w * (A[NN + pn] - w * a);     A[NN + top] = s1;
                    if (CHp > 2) { a = A[2*NN + top]; s2 = a + w * (A[2*NN + pn] - w * a); A[2*NN + top] = s2; }
                }
                for (int j = top + 1; j < top + len; j++) {
                    float w = wv[j];
                    float a = A[j];            s0 = a + w * (s0 - w * a);   A[j] = s0;
                    a = A[NN + j];             s1 = a + w * (s1 - w * a);   A[NN + j] = s1;
                    if (CHp > 2) { a = A[2*NN + j]; s2 = a + w * (s2 - w * a); A[2*NN + j] = s2; }
                }
            }
            __syncthreads();
        }
        #undef CBGET
        // normalize + scatter (stage0 -> tree1 chain order; stage1 -> AS2)
        for (int t = tid; t < NN*nreal; t += DP_T) {
            int c = t / NN, i = t - c*NN;
            float val = A[c*NN + i] / A[nreal*NN + i];
            if (st == 0) {
                g_f1[((size_t)b*NCH + cbase + c)*NN + g_perm01[b*NN + i]] = val;
            } else {
                g_AS2[(size_t)b*NCH*NN + (size_t)(cbase + c)*NN + g_ordC[1][b*NN + i]] = val;
            }
        }
        __syncthreads();
    }
}

__global__ void k_zero_acc() { g_acc[0] = 0.0; g_acc[1] = 0.0; }

__global__ __launch_bounds__(256) void k_loss(const float* __restrict__ roi) {
    double lsum = 0.0, nsum = 0.0;
    int stride = gridDim.x * blockDim.x;
    for (int idx = blockIdx.x*blockDim.x + threadIdx.x; idx < BN*NCH*NN; idx += stride) {
        int v = idx % NN;
        int bc = idx / NN;
        int c = bc % NCH, b = bc / NCH;
        int h = v / WW, wd = v % WW;
        float r = roi[b*(2*HH)*(2*WW) + (2*h)*(2*WW) + 2*wd];
        lsum += (double)(r * fabsf(g_prob[idx] - g_AS2[idx]));
        if (c == 0) nsum += (double)r;
    }
    __shared__ double shl[256], shn[256];
    int tid = threadIdx.x;
    shl[tid] = lsum; shn[tid] = nsum;
    __syncthreads();
    for (int off = 128; off > 0; off >>= 1) {
        if (tid < off) { shl[tid] += shl[tid+off]; shn[tid] += shn[tid+off]; }
        __syncthreads();
    }
    if (tid == 0) {
        atomicAdd(&g_acc[0], shl[0]);
        atomicAdd(&g_acc[1], shn[0]);
    }
}

__global__ void k_write(float* out) {
    double n = g_acc[1];
    out[0] = (n > 0.0) ? (float)(g_acc[0] / n) : 0.0f;
}

// ---------------- launch ----------------
extern "C" void kernel_launch(void* const* d_in, const int* in_sizes, int n_in,
                              void* d_out, int out_size) {
    const float *preds = nullptr, *lowf = nullptr, *highf = nullptr, *roi = nullptr;
    for (int i = 0; i < n_in; i++) {
        switch (in_sizes[i]) {
            case BN*NCH*NN:        preds = (const float*)d_in[i]; break;
            case BN*CLOW*NN:       lowf  = (const float*)d_in[i]; break;
            case BN*CHIGH*NN:      highf = (const float*)d_in[i]; break;
            case BN*(2*HH)*(2*WW): roi   = (const float*)d_in[i]; break;
        }
    }
    float* out = (float*)d_out;

    static int attr_done = 0;
    if (!attr_done) {
        cudaFuncSetAttribute(k_boruvka_both, cudaFuncAttributeMaxDynamicSharedMemorySize, SMEM_BORUVKA);
        cudaFuncSetAttribute(k_bfs_both,     cudaFuncAttributeMaxDynamicSharedMemorySize, BFS_SMEM);
        cudaFuncSetAttribute(k_chains,       cudaFuncAttributeMaxDynamicSharedMemorySize, CH_SMEM);
        cudaFuncSetAttribute(k_treedp,       cudaFuncAttributeMaxDynamicSharedMemorySize, DP_SMEM);
        attr_done = 1;
    }

    k_sigmoid<<<(BN*NCH*NN + 255)/256, 256>>>(preds);
    k_transpose<<<dim3(NN/32, CHIGH/32, BN), dim3(32,32)>>>(highf);

    k_edgew_low <<<(BN*EE + 127)/128, 128>>>(lowf);
    k_edgew_high<<<(BN*EE*32 + 255)/256, 256>>>();

    k_boruvka_both<<<2*BN, 1024, SMEM_BORUVKA>>>();
    k_bfs_both<<<2*BN, 256, BFS_SMEM>>>();
    k_chains<<<2*BN, 256, CH_SMEM>>>();

    k_nodew_low <<<(BN*NN + 127)/128, 128>>>(lowf);
    k_nodew_high<<<(BN*NN*32 + 255)/256, 256>>>();

    k_perm01  <<<(BN*NN + 255)/256, 256>>>();
    k_permute0<<<(BN*NN + 255)/256, 256>>>();

    k_treedp<<<BN*NGROUP, DP_T, DP_SMEM>>>();

    k_zero_acc<<<1, 1>>>();
    k_loss<<<1024, 256>>>(roi);
    k_write<<<1, 1>>>(out);
    (void)out_size;
}

// round 9
// speedup vs baseline: 1.9886x; 1.9886x over previous
#include <cuda_runtime.h>
#include <math.h>

#define BN 4
#define HH 96
#define WW 96
#define NN (HH*WW)        // 9216
#define EH (HH*(WW-1))    // 9120
#define EV ((HH-1)*WW)    // 9120
#define EE (EH+EV)        // 18240  (< 2^15)
#define NCH 21
#define CLOW 3
#define CHIGH 512
#define ROOT ((HH/2)*WW + (WW/2))   // center rooting: filter is root-invariant,
                                    // halves BFS depth vs corner node 0
#define NGROUP 11         // channel groups for DP: 10 groups of 2 + 1 group of 1
#define DP_T 256
#define LVCAP (NN+2)
#define DP_SMEM (3*NN*4 + NN*4 + NN*4 + LVCAP*4)   // A + wv + topo + lvl = 221192 B
#define BFS_SMEM (NN + 3*NN*4)                      // flags + ord + par + topo = 119808 B
#define SMEM_BORUVKA (NN*16)                        // bw(8) + cp(4) + lk(4) = 147456 B

// ---------------- device scratch ----------------
__device__ float  g_prob[BN*NCH*NN];
__device__ float  g_AS2 [BN*NCH*NN];
__device__ float  g_hft [(size_t)BN*NN*CHIGH];      // high feats transposed [b][n][c]
__device__ unsigned long long g_wkey[2][BN*EE];     // fused (weight_bits & ~0x7FFF) | edge
__device__ int    g_mst [2][BN*EE];
__device__ int    g_ord [2][BN*NN];       // position -> node
__device__ int    g_par [2][BN*NN];       // node -> parent node (-1 root)
__device__ unsigned g_topo[2][BN*NN];     // position -> pp | cs<<14 | cn<<28
__device__ float  g_wpos[2][BN*NN];       // position -> parent-edge weight (root 0)
__device__ int    g_lvl [2][BN*(NN+2)];
__device__ int    g_nlev[2][BN];
__device__ int    g_posN1[BN*NN];         // tree1: node -> position
__device__ int    g_perm01[BN*NN];        // tree0 pos -> tree1 pos
__device__ float  g_f0[BN*NCH*NN];        // stage0 features [b][c][pos0]
__device__ float  g_f1[BN*NCH*NN];        // stage1 features [b][c][pos1]
__device__ double g_acc[2];

__device__ __forceinline__ void edge_ep(int e, int& a, int& b) {
    if (e < EH) { int r = e / (WW-1), c = e % (WW-1); a = r*WW + c; b = a + 1; }
    else        { int j = e - EH;                      a = j;        b = j + WW; }
}
__device__ __forceinline__ void twosum(float& s, float& comp, float p) {
    float t = s + p;
    float z = t - s;
    float e = (s - (t - z)) + (p - z);
    s = t; comp += e;
}
// fused key: weight bit-pattern (positive double => order-preserving) with the
// low 15 bits replaced by the edge index. Perturbation 2^-37 relative; distinct
// continuous weights differ by ~1e-5 relative => ordering/MST unchanged.
__device__ __forceinline__ unsigned long long fuse_key(double w, int e) {
    return ((unsigned long long)__double_as_longlong(w) & 0xFFFFFFFFFFFF8000ull)
           | (unsigned long long)e;
}

// ---------------- kernels ----------------

__global__ void k_sigmoid(const float* __restrict__ preds) {
    int i = blockIdx.x*blockDim.x + threadIdx.x;
    if (i < BN*NCH*NN) g_prob[i] = 1.0f / (1.0f + expf(-preds[i]));
}

// tiled transpose: highf [b][c][n] -> g_hft [b][n][c]
__global__ void k_transpose(const float* __restrict__ hf) {
    __shared__ float tile[32][33];
    int b = blockIdx.z;
    int n0 = blockIdx.x*32, c0 = blockIdx.y*32;
    const float* src = hf + (size_t)b*CHIGH*NN;
    tile[threadIdx.y][threadIdx.x] = src[(size_t)(c0+threadIdx.y)*NN + n0+threadIdx.x];
    __syncthreads();
    g_hft[((size_t)b*NN + n0+threadIdx.y)*CHIGH + c0+threadIdx.x] = tile[threadIdx.x][threadIdx.y];
}

// low tree: exact double (C=3), fused key out
__global__ void k_edgew_low(const float* __restrict__ feat) {
    int i = blockIdx.x*blockDim.x + threadIdx.x;
    if (i >= BN*EE) return;
    int b = i / EE, e = i % EE;
    int a, bb; edge_ep(e, a, bb);
    const float* f = feat + (size_t)b * CLOW * NN;
    double s = 0.0;
    #pragma unroll
    for (int c = 0; c < CLOW; c++) {
        double d = (double)f[c*NN + a] - (double)f[c*NN + bb];
        s += d * d;
    }
    g_wkey[0][i] = fuse_key(s, e);
}

// high tree: warp per edge, float4 loads, compensated fp32 + double warp reduce.
__global__ __launch_bounds__(256) void k_edgew_high() {
    int w = (blockIdx.x*blockDim.x + threadIdx.x) >> 5;
    int lane = threadIdx.x & 31;
    if (w >= BN*EE) return;
    int b = w / EE, e = w % EE;
    int a, bb; edge_ep(e, a, bb);
    const float4* fa = (const float4*)(g_hft + ((size_t)b*NN + a)*CHIGH);
    const float4* fb = (const float4*)(g_hft + ((size_t)b*NN + bb)*CHIGH);
    float s = 0.f, comp = 0.f;
    #pragma unroll
    for (int k = 0; k < 4; k++) {
        float4 x = fa[lane + 32*k];
        float4 y = fb[lane + 32*k];
        float d0 = x.x - y.x, d1 = x.y - y.y, d2 = x.z - y.z, d3 = x.w - y.w;
        twosum(s, comp, d0*d0);
        twosum(s, comp, d1*d1);
        twosum(s, comp, d2*d2);
        twosum(s, comp, d3*d3);
    }
    double v = (double)s + (double)comp;
    #pragma unroll
    for (int off = 16; off; off >>= 1) v += __shfl_down_sync(0xffffffffu, v, off);
    if (lane == 0) g_wkey[1][w] = fuse_key(v, e);
}

// Boruvka MST, single-phase (fused keys), one block per (tree,batch), smem scratch.
__global__ __launch_bounds__(1024) void k_boruvka_both() {
    int b = blockIdx.x & 3, tree = blockIdx.x >> 2;
    int tid = threadIdx.x, T = blockDim.x;
    const unsigned long long* wk = g_wkey[tree] + b*EE;
    int* mf = g_mst[tree] + b*EE;

    extern __shared__ char smraw[];
    unsigned long long* bw = (unsigned long long*)smraw;   // NN*8
    int* cp = (int*)(smraw + NN*8);                         // NN*4
    int* lk = cp + NN;                                      // NN*4

    for (int v = tid; v < NN; v += T) cp[v] = v;
    for (int e = tid; e < EE; e += T) mf[e] = 0;
    __syncthreads();

    __shared__ int s_any, s_chg;
    for (int round = 0; round < 14; round++) {
        for (int v = tid; v < NN; v += T) {
            bw[v] = 0xFFFFFFFFFFFFFFFFull;
            lk[v] = v;
        }
        if (tid == 0) s_any = 0;
        __syncthreads();

        // per-component min (weight,edge) in one scan
        for (int e = tid; e < EE; e += T) {
            int a, bb; edge_ep(e, a, bb);
            int ca = cp[a], cb = cp[bb];
            if (ca != cb) {
                unsigned long long k = wk[e];
                atomicMin(&bw[ca], k);
                atomicMin(&bw[cb], k);
                s_any = 1;
            }
        }
        __syncthreads();
        if (!s_any) break;

        // hooking
        for (int v = tid; v < NN; v += T) {
            if (cp[v] == v && bw[v] != 0xFFFFFFFFFFFFFFFFull) {
                int e = (int)(bw[v] & 0x7FFFull);
                int a, bb; edge_ep(e, a, bb);
                int ca = cp[a], cb = cp[bb];
                lk[v] = (ca == v) ? cb : ca;
                mf[e] = 1;
            }
        }
        __syncthreads();

        // break mutual 2-cycles
        for (int v = tid; v < NN; v += T) {
            int o = lk[v];
            if (o != v && lk[o] == v && v < o) lk[v] = v;
        }
        __syncthreads();

        // pointer jumping
        for (int it = 0; it < 20; it++) {
            if (tid == 0) s_chg = 0;
            __syncthreads();
            for (int v = tid; v < NN; v += T) {
                int l = lk[v]; int ll = lk[l];
                if (l != ll) { lk[v] = ll; s_chg = 1; }
            }
            __syncthreads();
            if (!s_chg) break;
        }
        for (int v = tid; v < NN; v += T) cp[v] = lk[cp[v]];
        __syncthreads();
    }
}

// BFS (rooted at center) with contiguous child ranges + packed topology, smem state.
__global__ __launch_bounds__(256) void k_bfs_both() {
    int b = blockIdx.x & 3, tr = blockIdx.x >> 2;
    int tid = threadIdx.x, T = blockDim.x;
    extern __shared__ char sm[];
    unsigned char* flg = (unsigned char*)sm;        // NN
    int* ord = (int*)(sm + NN);                     // NN
    int* par = ord + NN;                            // NN (node -> parent node)
    unsigned* topo = (unsigned*)(par + NN);         // NN (pp | cs<<14 | cn<<28)
    const int* mf = g_mst[tr] + b*EE;

    for (int v = tid; v < NN; v += T) {
        int r = v / WW, c = v % WW;
        unsigned f = 0;
        if (c > 0      && mf[r*(WW-1) + c - 1])  f |= 1u;
        if (c < WW-1   && mf[r*(WW-1) + c])      f |= 2u;
        if (r > 0      && mf[EH + (r-1)*WW + c]) f |= 4u;
        if (r < HH-1   && mf[EH + r*WW + c])     f |= 8u;
        flg[v] = (unsigned char)f;
        topo[v] = 0u;
    }
    __shared__ int s_cnt;
    if (tid == 0) {
        ord[0] = ROOT; par[ROOT] = -1;
        g_lvl[tr][b*(NN+2)] = 0; g_lvl[tr][b*(NN+2)+1] = 1;
    }
    __syncthreads();

    int cur = 0, end = 1, d = 0;
    while (true) {
        if (tid == 0) s_cnt = 0;
        __syncthreads();
        for (int i = cur + tid; i < end; i += T) {
            int u = ord[i]; int pu = par[u];
            unsigned f = flg[u];
            int tmp[4]; int m = 0;
            if (f & 1u)  { int nb = u - 1;  if (nb != pu) tmp[m++] = nb; }
            if (f & 2u)  { int nb = u + 1;  if (nb != pu) tmp[m++] = nb; }
            if (f & 4u)  { int nb = u - WW; if (nb != pu) tmp[m++] = nb; }
            if (f & 8u)  { int nb = u + WW; if (nb != pu) tmp[m++] = nb; }
            int base = end + atomicAdd(&s_cnt, m);
            topo[i] |= ((unsigned)base << 14) | ((unsigned)m << 28);
            for (int j = 0; j < m; j++) {
                ord[base + j] = tmp[j];
                par[tmp[j]] = u;
                topo[base + j] = (unsigned)i;   // pp field; cs/cn filled next level
            }
        }
        __syncthreads();
        int cnt = s_cnt;
        if (tid == 0) g_lvl[tr][b*(NN+2) + d + 2] = end + cnt;
        if (cnt == 0) { if (tid == 0) g_nlev[tr][b] = d + 1; break; }
        cur = end; end += cnt; d++;
        __syncthreads();
    }
    __syncthreads();
    for (int v = tid; v < NN; v += T) {
        g_ord[tr][b*NN + v] = ord[v];
        g_par[tr][b*NN + v] = par[v];
        g_topo[tr][b*NN + v] = topo[v];
    }
}

// node weights (position-indexed). low: thread per position.
__global__ void k_nodew_low(const float* __restrict__ feat) {
    int i = blockIdx.x*blockDim.x + threadIdx.x;
    if (i >= BN*NN) return;
    int b = i / NN;
    int v = g_ord[0][i];
    int pu = g_par[0][b*NN + v];
    float wv = 0.0f;
    if (pu >= 0) {
        const float* f = feat + (size_t)b * CLOW * NN;
        float ss = 0.0f;
        #pragma unroll
        for (int c = 0; c < CLOW; c++) {
            float d = f[c*NN + v] - f[c*NN + pu];
            ss += d * d;
        }
        wv = expf(-ss / 0.02f);
    }
    g_wpos[0][i] = wv;
}

// high: warp per position, float4 loads from transposed feats.
__global__ __launch_bounds__(256) void k_nodew_high() {
    int w = (blockIdx.x*blockDim.x + threadIdx.x) >> 5;
    int lane = threadIdx.x & 31;
    if (w >= BN*NN) return;
    int b = w / NN;
    int v = g_ord[1][w];
    int pu = g_par[1][b*NN + v];
    float wv = 0.0f;
    if (pu >= 0) {
        const float4* fa = (const float4*)(g_hft + ((size_t)b*NN + v)*CHIGH);
        const float4* fb = (const float4*)(g_hft + ((size_t)b*NN + pu)*CHIGH);
        float ss = 0.0f;
        #pragma unroll
        for (int k = 0; k < 4; k++) {
            float4 x = fa[lane + 32*k];
            float4 y = fb[lane + 32*k];
            float d0 = x.x - y.x, d1 = x.y - y.y, d2 = x.z - y.z, d3 = x.w - y.w;
            ss += d0*d0 + d1*d1 + d2*d2 + d3*d3;
        }
        #pragma unroll
        for (int off = 16; off; off >>= 1) ss += __shfl_down_sync(0xffffffffu, ss, off);
        wv = expf(-ss);   // sigma = 1
    }
    if (lane == 0) g_wpos[1][w] = wv;
}

__global__ void k_invord1() {
    int i = blockIdx.x*blockDim.x + threadIdx.x;
    if (i < BN*NN) g_posN1[(i/NN)*NN + g_ord[1][i]] = i % NN;
}
__global__ void k_perm01() {
    int i = blockIdx.x*blockDim.x + threadIdx.x;
    if (i < BN*NN) g_perm01[i] = g_posN1[(i/NN)*NN + g_ord[0][i]];
}
// prob -> [b][c][pos0]
__global__ void k_permute0() {
    int i = blockIdx.x*blockDim.x + threadIdx.x;
    if (i >= BN*NN) return;
    int b = i / NN, p = i % NN;
    int u = g_ord[0][i];
    #pragma unroll
    for (int c = 0; c < NCH; c++)
        g_f0[((size_t)b*NCH + c)*NN + p] = g_prob[((size_t)b*NCH + c)*NN + u];
}

// Fused two-stage tree DP, all state in shared memory, small-level warp runs.
__global__ __launch_bounds__(DP_T) void k_treedp() {
    int b = blockIdx.x / NGROUP, g = blockIdx.x % NGROUP;
    int tid = threadIdx.x;
    int nreal = (g == NGROUP-1) ? (NCH - 2*(NGROUP-1)) : 2;   // 2×10 + 1
    int cbase = g*2;
    int CH = nreal + 1;

    extern __shared__ char smraw2[];
    float* A      = (float*)smraw2;                  // 3*NN
    float* wv     = (float*)(smraw2 + 3*NN*4);       // NN
    unsigned* tp  = (unsigned*)(smraw2 + 4*NN*4);    // NN
    int* slvl     = (int*)(smraw2 + 5*NN*4);         // LVCAP

    for (int st = 0; st < 2; st++) {
        const int tr = st;
        const float* FP = (st == 0 ? g_f0 : g_f1) + (size_t)b*NCH*NN;
        int D = g_nlev[tr][b];

        for (int i = tid; i < NN; i += DP_T) {
            wv[i] = g_wpos[tr][b*NN + i];
            tp[i] = g_topo[tr][b*NN + i];
        }
        for (int i = tid; i < D + 1; i += DP_T) slvl[i] = g_lvl[tr][b*(NN+2) + i];
        for (int c = 0; c < nreal; c++)
            for (int i = tid; i < NN; i += DP_T) A[c*NN + i] = FP[(size_t)(cbase + c)*NN + i];
        for (int i = tid; i < NN; i += DP_T) A[nreal*NN + i] = 1.0f;
        __syncthreads();

        // up: children before parents
        {
            int d = D - 1;
            while (d >= 0) {
                int lo = slvl[d], cnt = slvl[d+1] - lo, m = cnt * CH;
                if (m > 32) {
                    for (int t = tid; t < m; t += DP_T) {
                        int c = t / cnt, i = lo + (t - c*cnt);
                        unsigned u = tp[i];
                        int cs = (u >> 14) & 0x3FFF, cn = u >> 28;
                        float acc = A[c*NN + i];
                        for (int j = cs; j < cs + cn; j++) acc += wv[j] * A[c*NN + j];
                        A[c*NN + i] = acc;
                    }
                    __syncthreads();
                    d--;
                } else {
                    // maximal run of small levels, processed by warp 0
                    int e = d;
                    while (e > 0 && (slvl[e] - slvl[e-1]) * CH <= 32) e--;
                    if (tid < 32) {
                        for (int dd = d; dd >= e; dd--) {
                            int lo2 = slvl[dd], cnt2 = slvl[dd+1] - lo2, m2 = cnt2 * CH;
                            if (tid < m2) {
                                int c = tid / cnt2, i = lo2 + (tid - c*cnt2);
                                unsigned u = tp[i];
                                int cs = (u >> 14) & 0x3FFF, cn = u >> 28;
                                float acc = A[c*NN + i];
                                for (int j = cs; j < cs + cn; j++) acc += wv[j] * A[c*NN + j];
                                A[c*NN + i] = acc;
                            }
                            __syncwarp();
                        }
                    }
                    __syncthreads();
                    d = e - 1;
                }
            }
        }
        // down: parents before children (root level identity)
        {
            int d = 1;
            while (d < D) {
                int lo = slvl[d], cnt = slvl[d+1] - lo, m = cnt * CH;
                if (m > 32) {
                    for (int t = tid; t < m; t += DP_T) {
                        int c = t / cnt, i = lo + (t - c*cnt);
                        int pp = tp[i] & 0x3FFF;
                        float av = A[c*NN + i];
                        float wu = wv[i];
                        A[c*NN + i] = av + wu * (A[c*NN + pp] - wu * av);
                    }
                    __syncthreads();
                    d++;
                } else {
                    int e = d;
                    while (e < D - 1 && (slvl[e+2] - slvl[e+1]) * CH <= 32) e++;
                    if (tid < 32) {
                        for (int dd = d; dd <= e; dd++) {
                            int lo2 = slvl[dd], cnt2 = slvl[dd+1] - lo2, m2 = cnt2 * CH;
                            if (tid < m2) {
                                int c = tid / cnt2, i = lo2 + (tid - c*cnt2);
                                int pp = tp[i] & 0x3FFF;
                                float av = A[c*NN + i];
                                float wu = wv[i];
                                A[c*NN + i] = av + wu * (A[c*NN + pp] - wu * av);
                            }
                            __syncwarp();
                        }
                    }
                    __syncthreads();
                    d = e + 1;
                }
            }
        }
        // normalize + write
        for (int t = tid; t < NN*nreal; t += DP_T) {
            int c = t / NN, i = t - c*NN;
            float val = A[c*NN + i] / A[nreal*NN + i];
            if (st == 0) {
                g_f1[((size_t)b*NCH + cbase + c)*NN + g_perm01[b*NN + i]] = val;
            } else {
                g_AS2[(size_t)b*NCH*NN + (size_t)(cbase + c)*NN + g_ord[1][b*NN + i]] = val;
            }
        }
        __syncthreads();
    }
}

__global__ void k_zero_acc() { g_acc[0] = 0.0; g_acc[1] = 0.0; }

__global__ __launch_bounds__(256) void k_loss(const float* __restrict__ roi) {
    double lsum = 0.0, nsum = 0.0;
    int stride = gridDim.x * blockDim.x;
    for (int idx = blockIdx.x*blockDim.x + threadIdx.x; idx < BN*NCH*NN; idx += stride) {
        int v = idx % NN;
        int bc = idx / NN;
        int c = bc % NCH, b = bc / NCH;
        int h = v / WW, wd = v % WW;
        float r = roi[b*(2*HH)*(2*WW) + (2*h)*(2*WW) + 2*wd];
        lsum += (double)(r * fabsf(g_prob[idx] - g_AS2[idx]));
        if (c == 0) nsum += (double)r;
    }
    __shared__ double shl[256], shn[256];
    int tid = threadIdx.x;
    shl[tid] = lsum; shn[tid] = nsum;
    __syncthreads();
    for (int off = 128; off > 0; off >>= 1) {
        if (tid < off) { shl[tid] += shl[tid+off]; shn[tid] += shn[tid+off]; }
        __syncthreads();
    }
    if (tid == 0) {
        atomicAdd(&g_acc[0], shl[0]);
        atomicAdd(&g_acc[1], shn[0]);
    }
}

__global__ void k_write(float* out) {
    double n = g_acc[1];
    out[0] = (n > 0.0) ? (float)(g_acc[0] / n) : 0.0f;
}

// ---------------- launch ----------------
extern "C" void kernel_launch(void* const* d_in, const int* in_sizes, int n_in,
                              void* d_out, int out_size) {
    const float *preds = nullptr, *lowf = nullptr, *highf = nullptr, *roi = nullptr;
    for (int i = 0; i < n_in; i++) {
        switch (in_sizes[i]) {
            case BN*NCH*NN:        preds = (const float*)d_in[i]; break;
            case BN*CLOW*NN:       lowf  = (const float*)d_in[i]; break;
            case BN*CHIGH*NN:      highf = (const float*)d_in[i]; break;
            case BN*(2*HH)*(2*WW): roi   = (const float*)d_in[i]; break;
        }
    }
    float* out = (float*)d_out;

    static int attr_done = 0;
    if (!attr_done) {
        cudaFuncSetAttribute(k_boruvka_both, cudaFuncAttributeMaxDynamicSharedMemorySize, SMEM_BORUVKA);
        cudaFuncSetAttribute(k_bfs_both,     cudaFuncAttributeMaxDynamicSharedMemorySize, BFS_SMEM);
        cudaFuncSetAttribute(k_treedp,       cudaFuncAttributeMaxDynamicSharedMemorySize, DP_SMEM);
        attr_done = 1;
    }

    k_sigmoid<<<(BN*NCH*NN + 255)/256, 256>>>(preds);
    k_transpose<<<dim3(NN/32, CHIGH/32, BN), dim3(32,32)>>>(highf);

    k_edgew_low <<<(BN*EE + 127)/128, 128>>>(lowf);
    k_edgew_high<<<(BN*EE*32 + 255)/256, 256>>>();

    k_boruvka_both<<<2*BN, 1024, SMEM_BORUVKA>>>();
    k_bfs_both<<<2*BN, 256, BFS_SMEM>>>();

    k_nodew_low <<<(BN*NN + 127)/128, 128>>>(lowf);
    k_nodew_high<<<(BN*NN*32 + 255)/256, 256>>>();

    k_invord1 <<<(BN*NN + 255)/256, 256>>>();
    k_perm01  <<<(BN*NN + 255)/256, 256>>>();
    k_permute0<<<(BN*NN + 255)/256, 256>>>();

    k_treedp<<<BN*NGROUP, DP_T, DP_SMEM>>>();

    k_zero_acc<<<1, 1>>>();
    k_loss<<<1024, 256>>>(roi);
    k_write<<<1, 1>>>(out);
    (void)out_size;
}